// round 13
// baseline (speedup 1.0000x reference)
#include <cuda_runtime.h>
#include <math.h>

#define BB 16
#define AA 8400
#define MM 64
#define NCC 80
#define TOPK_K 10
#define EPS_G 1e-9f
#define EPS_C 1e-7f
#define NCHUNK 33              // phase2: ceil(8400/256)
#define WSTRIDE 12             // winners per gt: 10 topk + 1 quirk + pad
#define CAPL 768               // max fg anchors per batch (<= winner slots)
#define NCAND 5                // max candidates per thread (ceil(1035/256))

// -------- scratch (device globals; no allocation allowed) --------
__device__ int g_win[BB * MM * WSTRIDE];   // winner anchor indices, -1 = empty
__device__ int g_posal[BB * MM];           // pos_align   (float bits, >=0)
__device__ int g_posov[BB * MM];           // pos_overlap (float bits, >=0)
__device__ int g_cnt[BB];                  // fg list counts
__device__ int g_done[BB];                 // per-batch finished-block counters
__device__ int g_la[BB * CAPL];            // fg entries: a | tgt<<14 | lab<<20
__device__ float g_ln[BB * CAPL];          // fg entries: align metric (num)

__device__ __forceinline__ float ciou_full(float gx1, float gy1, float gx2, float gy2,
                                           float px1, float py1, float px2, float py2)
{
    const float w1 = gx2 - gx1;
    const float h1 = gy2 - gy1 + EPS_C;
    const float w2 = px2 - px1;
    const float h2 = py2 - py1 + EPS_C;
    const float iw = fminf(gx2, px2) - fmaxf(gx1, px1);
    const float ih = fminf(gy2, py2) - fmaxf(gy1, py1);
    const float inter = fmaxf(iw, 0.0f) * fmaxf(ih, 0.0f);
    const float uni = w1 * h1 + w2 * h2 - inter + EPS_C;
    const float iou = inter / uni;
    const float cw = fmaxf(gx2, px2) - fminf(gx1, px1);
    const float ch = fmaxf(gy2, py2) - fminf(gy1, py1);
    const float c2 = cw * cw + ch * ch + EPS_C;
    const float dx = px1 + px2 - gx1 - gx2;
    const float dy = py1 + py2 - gy1 - gy2;
    const float rho2 = (dx * dx + dy * dy) * 0.25f;
    const float dat = atanf(w2 / h2) - atanf(w1 / h1);
    const float v = (4.0f / (float)(M_PI * M_PI)) * dat * dat;
    const float alpha = v / (v - iou + (1.0f + EPS_C));
    return iou - (rho2 / c2 + v * alpha);
}

// ---------------- K-B: zero all scores (runs on side stream) ----------------
__global__ void __launch_bounds__(256)
fill_kernel(float* __restrict__ out_scores)
{
    const int idx = blockIdx.x * 256 + threadIdx.x;
    const int nthr = gridDim.x * 256;
    const float4 z4 = make_float4(0.0f, 0.0f, 0.0f, 0.0f);
    float4* s4 = (float4*)out_scores;
    const int ns4 = BB * AA * NCC / 4;
    for (int k = idx; k < ns4; k += nthr) s4[k] = z4;
}

// ---------------- Phase 1: per-(b,m) enumerate in-box anchors, topk ----------
__global__ void __launch_bounds__(256)
phase1_kernel(const float* __restrict__ pd_scores,
              const float* __restrict__ pd_bboxes,
              const int* __restrict__ gt_labels,
              const float* __restrict__ gt_bboxes,
              const float* __restrict__ mask_gt)
{
    __shared__ unsigned s_wtv[8][TOPK_K];
    __shared__ unsigned s_wta[8][TOPK_K];

    const int bm = blockIdx.x;
    const int b = bm >> 6;
    const int m = bm & 63;
    const int tid = threadIdx.x;
    const int warp = tid >> 5;
    const int lane = tid & 31;
    const unsigned full = 0xffffffffu;

    if (tid == 0) {
        g_posal[bm] = 0;
        g_posov[bm] = 0;
        if (m == 0) { g_cnt[b] = 0; g_done[b] = 0; }
    }

    const bool valid = mask_gt[bm] > 0.0f;
    if (!valid) {
        // metrics all zero -> no winners, no quirk (mask_pos_gt[0] is 0)
        if (tid < WSTRIDE) g_win[bm * WSTRIDE + tid] = -1;
        return;
    }

    const float4 gb = ((const float4*)gt_bboxes)[bm];
    const float gx1 = gb.x, gy1 = gb.y, gx2 = gb.z, gy2 = gb.w;
    const int   label = gt_labels[bm];

    const float w1 = gx2 - gx1;
    const float h1 = gy2 - gy1 + EPS_C;
    const float area1 = w1 * h1;
    const float at1 = atanf(w1 / h1);
    const float inv_pi2_4 = 4.0f / (float)(M_PI * M_PI);

    const float4* pb = (const float4*)(pd_bboxes + (size_t)b * AA * 4);
    const float*  ps = pd_scores + (size_t)b * AA * NCC;

    // anchor lattice: level L has n=640/s points per axis at ((c+0.5)*s)
    const int   Lbase[3] = {0, 6400, 8000};
    const int   Ln[3]    = {80, 40, 20};
    const float Lsf[3]   = {8.0f, 16.0f, 32.0f};

    int cmin[3], rmin[3], Wd[3], cum[4];
    float invW[3];
    cum[0] = 0;
#pragma unroll
    for (int L = 0; L < 3; L++) {
        const float inv_s = 1.0f / Lsf[L];
        const int c0 = max(0, (int)floorf(gx1 * inv_s) - 1);
        const int c1 = min(Ln[L] - 1, (int)ceilf(gx2 * inv_s));
        const int r0 = max(0, (int)floorf(gy1 * inv_s) - 1);
        const int r1 = min(Ln[L] - 1, (int)ceilf(gy2 * inv_s));
        const int w = c1 - c0 + 1;
        const int h = r1 - r0 + 1;
        const int cnt = (w > 0 && h > 0) ? w * h : 0;
        cmin[L] = c0; rmin[L] = r0; Wd[L] = (w > 0) ? w : 1;
        invW[L] = 1.0f / (float)Wd[L];
        cum[L + 1] = cum[L] + cnt;
    }
    const int T = cum[3];

    // per-thread register candidate store (<= NCAND candidates per thread)
    unsigned cval[NCAND], canc[NCAND];
#pragma unroll
    for (int k = 0; k < NCAND; k++) { cval[k] = 0u; canc[k] = 0xFFFFFFFFu; }
    int cnt = 0;

    for (int t = tid; t < T; t += 256) {
        const int L = (t < cum[1]) ? 0 : ((t < cum[2]) ? 1 : 2);
        const int local = t - cum[L];
        // cheap division: float reciprocal + correction (exact; local <= 1035)
        int q = (int)((float)local * invW[L]);
        int rem = local - q * Wd[L];
        if (rem < 0) { q--; rem += Wd[L]; }
        else if (rem >= Wd[L]) { q++; rem -= Wd[L]; }
        const int row = rmin[L] + q;
        const int col = cmin[L] + rem;
        const float s = Lsf[L];
        const float ax = ((float)col + 0.5f) * s;   // bit-exact vs anc input
        const float ay = ((float)row + 0.5f) * s;
        const float d = fminf(fminf(ax - gx1, ay - gy1), fminf(gx2 - ax, gy2 - ay));
        if (!(d > EPS_G)) continue;
        const int a = Lbase[L] + row * Ln[L] + col;
        const float4 p = pb[a];
        const float w2 = p.z - p.x;
        const float h2 = p.w - p.y + EPS_C;
        const float iw = fminf(gx2, p.z) - fmaxf(gx1, p.x);
        const float ih = fminf(gy2, p.w) - fmaxf(gy1, p.y);
        const float inter = fmaxf(iw, 0.0f) * fmaxf(ih, 0.0f);
        const float uni = area1 + w2 * h2 - inter + EPS_C;
        const float iou = inter / uni;
        const float cw = fmaxf(gx2, p.z) - fminf(gx1, p.x);
        const float ch = fmaxf(gy2, p.w) - fminf(gy1, p.y);
        const float c2 = cw * cw + ch * ch + EPS_C;
        const float dx = p.x + p.z - gx1 - gx2;
        const float dy = p.y + p.w - gy1 - gy2;
        const float rho2 = (dx * dx + dy * dy) * 0.25f;
        const float dat = atanf(w2 / h2) - at1;
        const float v = inv_pi2_4 * dat * dat;
        const float alpha = v / (v - iou + (1.0f + EPS_C));
        const float ciou = iou - (rho2 / c2 + v * alpha);
        const float ovl = fmaxf(ciou, 0.0f);
        if (ovl <= 0.0f) continue;
        const float sc = ps[(size_t)a * NCC + label];
        const float o2 = ovl * ovl;
        const float met = sqrtf(sc) * (o2 * o2 * o2);
        if (met > EPS_G) {
#pragma unroll
            for (int k = 0; k < NCAND; k++)
                if (cnt == k) { cval[k] = __float_as_uint(met); canc[k] = (unsigned)a; }
            cnt++;
        }
    }

    // ---- sort the <=5 register candidates descending by (v, then a asc) ----
#define CSWAP(i, j) { \
        const bool sw = (cval[j] > cval[i]) || (cval[j] == cval[i] && canc[j] < canc[i]); \
        const unsigned tv = sw ? cval[j] : cval[i]; \
        const unsigned ta = sw ? canc[j] : canc[i]; \
        cval[j] = sw ? cval[i] : cval[j]; \
        canc[j] = sw ? canc[i] : canc[j]; \
        cval[i] = tv; canc[i] = ta; }
    CSWAP(0, 1) CSWAP(3, 4) CSWAP(2, 4) CSWAP(2, 3) CSWAP(1, 4)
    CSWAP(0, 3) CSWAP(0, 2) CSWAP(1, 3) CSWAP(1, 2)
#undef CSWAP

    // ---- per-warp sorted top-10 via 10 REDUX rounds (no block barriers) ----
#pragma unroll
    for (int r = 0; r < TOPK_K; r++) {
        const unsigned bv = cval[0];
        const unsigned ba = canc[0];
        const unsigned vmax = __reduce_max_sync(full, bv);
        const unsigned acand = (bv == vmax) ? ba : 0xFFFFFFFFu;
        const unsigned amin = __reduce_min_sync(full, acand);
        if (lane == 0) { s_wtv[warp][r] = vmax; s_wta[warp][r] = amin; }
        // winner thread shifts its sorted list down one
        if (bv == vmax && ba == amin) {
#pragma unroll
            for (int k = 0; k < NCAND - 1; k++) { cval[k] = cval[k + 1]; canc[k] = canc[k + 1]; }
            cval[NCAND - 1] = 0u; canc[NCAND - 1] = 0xFFFFFFFFu;
        }
    }
    __syncthreads();

    // ---- warp 0: merge 8 sorted lists of 10 via xor-shuffle over 8 heads ----
    if (warp == 0) {
        int ptr = 0;
        int winners[TOPK_K];
        int kept = 0;
#pragma unroll
        for (int r = 0; r < TOPK_K; r++) {
            unsigned v = 0u, a = 0xFFFFFFFFu;
            if (lane < 8 && ptr < TOPK_K) { v = s_wtv[lane][ptr]; a = s_wta[lane][ptr]; }
            unsigned wv = v, wa = a;
#pragma unroll
            for (int off = 4; off; off >>= 1) {
                const unsigned ov = __shfl_xor_sync(full, wv, off);
                const unsigned oa = __shfl_xor_sync(full, wa, off);
                if (ov > wv || (ov == wv && oa < wa)) { wv = ov; wa = oa; }
            }
            if (v == wv && a == wa && lane < 8 && wv != 0u) ptr++;
            if (lane == 0) {
                winners[r] = (int)wa;
                if (__uint_as_float(wv) > EPS_G) kept = r + 1;
            }
        }
        if (lane == 0) {
            // reference quirk: dropped top-k slots scatter into anchor 0,
            // gated by mask_in_gts[0] & mask_pos_gt[0]
            if (kept < TOPK_K) {
                const float d0 = fminf(fminf(4.0f - gx1, 4.0f - gy1),
                                       fminf(gx2 - 4.0f, gy2 - 4.0f));
                if (d0 > EPS_G) winners[kept++] = 0;
            }
#pragma unroll
            for (int k = 0; k < WSTRIDE; k++)
                g_win[bm * WSTRIDE + k] = (k < kept) ? winners[k] : -1;
        }
    }
}

// ---------------- Phase 2: resolution + outputs + in-kernel score scatter ----
__global__ void __launch_bounds__(256)
phase2_kernel(const float* __restrict__ pd_scores,
              const float* __restrict__ pd_bboxes,
              const float* __restrict__ anc,
              const int* __restrict__ gt_labels,
              const float* __restrict__ gt_bboxes,
              const float* __restrict__ mask_gt,
              float* __restrict__ out_bboxes,
              float* __restrict__ out_scores,
              float* __restrict__ out_fg)
{
    __shared__ float4 s_gt[MM];
    __shared__ int s_lb[MM];
    __shared__ int s_ok[MM];
    __shared__ unsigned long long s_bits[256];
    __shared__ int s_last;

    const int b = blockIdx.x / NCHUNK;
    const int chunk = blockIdx.x - b * NCHUNK;
    const int tid = threadIdx.x;
    const int a0 = chunk * 256;

    if (tid < MM) {
        s_gt[tid] = ((const float4*)gt_bboxes)[b * MM + tid];
        s_lb[tid] = gt_labels[b * MM + tid];
        s_ok[tid] = mask_gt[b * MM + tid] > 0.0f;
    }
    s_bits[tid] = 0ull;
    __syncthreads();

    // membership from winner lists
    for (int j = tid; j < MM * WSTRIDE; j += 256) {
        const int w = g_win[b * MM * WSTRIDE + j];
        if (w >= a0 && w < a0 + 256)
            atomicOr(&s_bits[w - a0], 1ull << (j / WSTRIDE));
    }
    __syncthreads();

    const int a = a0 + tid;
    const int i = b * AA + a;

    if (a < AA) {
        const unsigned long long bits = s_bits[tid];
        int tgt = 0, fg = 0;
        float num = 0.0f;

        if (bits) {
            fg = 1;
            const float2 an = ((const float2*)anc)[a];
            const float4 p = ((const float4*)pd_bboxes)[(size_t)b * AA + a];
            if (__popcll(bits) == 1) {
                tgt = __ffsll((long long)bits) - 1;
            } else {
                // argmax over ALL m of masked clipped CIoU (first max wins)
                float best = -1.0f;
                int bi = 0;
                for (int mm = 0; mm < MM; mm++) {
                    float v = 0.0f;
                    if (s_ok[mm]) {
                        const float4 g = s_gt[mm];
                        const float d = fminf(fminf(an.x - g.x, an.y - g.y),
                                              fminf(g.z - an.x, g.w - an.y));
                        if (d > EPS_G) {
                            const float c = ciou_full(g.x, g.y, g.z, g.w,
                                                      p.x, p.y, p.z, p.w);
                            v = fmaxf(c, 0.0f);
                        }
                    }
                    if (v > best) { best = v; bi = mm; }
                }
                tgt = bi;
            }
            float ovl = 0.0f;
            const float4 g = s_gt[tgt];
            bool pos = false;
            if (s_ok[tgt]) {
                const float d = fminf(fminf(an.x - g.x, an.y - g.y),
                                      fminf(g.z - an.x, g.w - an.y));
                pos = d > EPS_G;
            }
            if (pos) {
                const float c = ciou_full(g.x, g.y, g.z, g.w, p.x, p.y, p.z, p.w);
                ovl = fmaxf(c, 0.0f);
                const float sc = pd_scores[((size_t)b * AA + a) * NCC + s_lb[tgt]];
                const float o2 = ovl * ovl;
                num = sqrtf(sc) * (o2 * o2 * o2);
            }
            atomicMax(&g_posal[b * MM + tgt], __float_as_int(num));
            atomicMax(&g_posov[b * MM + tgt], __float_as_int(ovl));
            // append to fg list for the batch-final score scatter
            int lab = s_lb[tgt];
            if (lab < 0) lab = 0;
            const int slot = atomicAdd(&g_cnt[b], 1);
            if (slot < CAPL) {
                g_la[b * CAPL + slot] = a | (tgt << 14) | (lab << 20);
                g_ln[b * CAPL + slot] = num;
            }
        }
        ((float4*)out_bboxes)[i] = s_gt[tgt];
        out_fg[i] = fg ? 1.0f : 0.0f;
    }

    // ---- per-batch completion: last block of batch b scatters its scores ----
    __threadfence();
    __syncthreads();
    if (tid == 0) {
        const int old = atomicAdd(&g_done[b], 1);
        s_last = (old == NCHUNK - 1) ? 1 : 0;
    }
    __syncthreads();
    if (s_last) {
        __threadfence();   // acquire prior batches' writes (pos arrays, lists)
        const int n = min(g_cnt[b], CAPL);
        for (int k = tid; k < n; k += 256) {
            const int e = g_la[b * CAPL + k];
            const int aa = e & 0x3FFF;
            const int tgt = (e >> 14) & 63;
            const int lab = (e >> 20) & 127;
            const float pa = __int_as_float(g_posal[b * MM + tgt]);
            const float po = __int_as_float(g_posov[b * MM + tgt]);
            const float norm = g_ln[b * CAPL + k] * po / (pa + EPS_G);
            out_scores[((size_t)b * AA + aa) * NCC + lab] = norm;
        }
    }
}

extern "C" void kernel_launch(void* const* d_in, const int* in_sizes, int n_in,
                              void* d_out, int out_size)
{
    const float* pd_scores = (const float*)d_in[0];   // (B, A, NC) f32
    const float* pd_bboxes = (const float*)d_in[1];   // (B, A, 4)  f32
    const float* anc       = (const float*)d_in[2];   // (A, 2)     f32
    const int*   gt_labels = (const int*)  d_in[3];   // (B, M, 1)  i32
    const float* gt_bboxes = (const float*)d_in[4];   // (B, M, 4)  f32
    const float* mask_gt   = (const float*)d_in[5];   // (B, M, 1)  f32

    float* out = (float*)d_out;
    float* out_bboxes = out;                                  // B*A*4
    float* out_scores = out + (size_t)BB * AA * 4;            // B*A*NC
    float* out_fg     = out + (size_t)BB * AA * (4 + NCC);    // B*A

    static cudaStream_t sB = nullptr;
    static cudaEvent_t eFork = nullptr, eJoin = nullptr;
    if (sB == nullptr) {
        cudaStreamCreateWithFlags(&sB, cudaStreamNonBlocking);
        cudaEventCreateWithFlags(&eFork, cudaEventDisableTiming);
        cudaEventCreateWithFlags(&eJoin, cudaEventDisableTiming);
    }

    // fork: score zero-fill runs on side stream, overlapped with phase1
    cudaEventRecord(eFork, 0);
    cudaStreamWaitEvent(sB, eFork, 0);
    fill_kernel<<<1050, 256, 0, sB>>>(out_scores);
    cudaEventRecord(eJoin, sB);

    phase1_kernel<<<BB * MM, 256>>>(pd_scores, pd_bboxes,
                                    gt_labels, gt_bboxes, mask_gt);

    // phase2 writes out_scores (per-batch final scatter) -> must follow fill
    cudaStreamWaitEvent(0, eJoin, 0);
    phase2_kernel<<<BB * NCHUNK, 256>>>(pd_scores, pd_bboxes, anc,
                                        gt_labels, gt_bboxes, mask_gt,
                                        out_bboxes, out_scores, out_fg);
}

// round 14
// speedup vs baseline: 1.0683x; 1.0683x over previous
#include <cuda_runtime.h>
#include <math.h>

#define BB 16
#define AA 8400
#define MM 64
#define NCC 80
#define TOPK_K 10
#define EPS_G 1e-9f
#define EPS_C 1e-7f
#define NCHUNK 33              // phase2: ceil(8400/256)
#define WSTRIDE 12             // winners per gt: 10 topk + 1 quirk + pad
#define CAPL 768               // max fg anchors per batch (<= winner slots)
#define NCAND 5                // max candidates per thread (ceil(1035/256))

// -------- scratch (device globals; no allocation allowed) --------
__device__ int g_win[BB * MM * WSTRIDE];   // winner anchor indices, -1 = empty
__device__ int g_posal[BB * MM];           // pos_align   (float bits, >=0)
__device__ int g_posov[BB * MM];           // pos_overlap (float bits, >=0)
__device__ int g_cnt[BB];                  // fg list counts
__device__ int g_done[BB];                 // per-batch finished-block counters
__device__ int g_la[BB * CAPL];            // fg entries: a | tgt<<14 | lab<<20
__device__ float g_ln[BB * CAPL];          // fg entries: align metric (num)

__device__ __forceinline__ float ciou_full(float gx1, float gy1, float gx2, float gy2,
                                           float px1, float py1, float px2, float py2)
{
    const float w1 = gx2 - gx1;
    const float h1 = gy2 - gy1 + EPS_C;
    const float w2 = px2 - px1;
    const float h2 = py2 - py1 + EPS_C;
    const float iw = fminf(gx2, px2) - fmaxf(gx1, px1);
    const float ih = fminf(gy2, py2) - fmaxf(gy1, py1);
    const float inter = fmaxf(iw, 0.0f) * fmaxf(ih, 0.0f);
    const float uni = w1 * h1 + w2 * h2 - inter + EPS_C;
    const float iou = inter / uni;
    const float cw = fmaxf(gx2, px2) - fminf(gx1, px1);
    const float ch = fmaxf(gy2, py2) - fminf(gy1, py1);
    const float c2 = cw * cw + ch * ch + EPS_C;
    const float dx = px1 + px2 - gx1 - gx2;
    const float dy = py1 + py2 - gy1 - gy2;
    const float rho2 = (dx * dx + dy * dy) * 0.25f;
    const float dat = atanf(w2 / h2) - atanf(w1 / h1);
    const float v = (4.0f / (float)(M_PI * M_PI)) * dat * dat;
    const float alpha = v / (v - iou + (1.0f + EPS_C));
    return iou - (rho2 / c2 + v * alpha);
}

// ---------------- Phase 1: per-(b,m) enumerate in-box anchors, topk ----------
__global__ void __launch_bounds__(256)
phase1_kernel(const float* __restrict__ pd_scores,
              const float* __restrict__ pd_bboxes,
              const int* __restrict__ gt_labels,
              const float* __restrict__ gt_bboxes,
              const float* __restrict__ mask_gt)
{
    __shared__ unsigned s_wtv[8][TOPK_K];
    __shared__ unsigned s_wta[8][TOPK_K];

    const int bm = blockIdx.x;
    const int b = bm >> 6;
    const int m = bm & 63;
    const int tid = threadIdx.x;
    const int warp = tid >> 5;
    const int lane = tid & 31;
    const unsigned full = 0xffffffffu;

    if (tid == 0) {
        g_posal[bm] = 0;
        g_posov[bm] = 0;
        if (m == 0) { g_cnt[b] = 0; g_done[b] = 0; }
    }

    const bool valid = mask_gt[bm] > 0.0f;
    if (!valid) {
        // metrics all zero -> no winners, no quirk (mask_pos_gt[0] is 0)
        if (tid < WSTRIDE) g_win[bm * WSTRIDE + tid] = -1;
        return;
    }

    const float4 gb = ((const float4*)gt_bboxes)[bm];
    const float gx1 = gb.x, gy1 = gb.y, gx2 = gb.z, gy2 = gb.w;
    const int   label = gt_labels[bm];

    const float w1 = gx2 - gx1;
    const float h1 = gy2 - gy1 + EPS_C;
    const float area1 = w1 * h1;
    const float at1 = atanf(w1 / h1);
    const float inv_pi2_4 = 4.0f / (float)(M_PI * M_PI);

    const float4* pb = (const float4*)(pd_bboxes + (size_t)b * AA * 4);
    const float*  ps = pd_scores + (size_t)b * AA * NCC;

    // anchor lattice: level L has n=640/s points per axis at ((c+0.5)*s)
    const int   Lbase[3] = {0, 6400, 8000};
    const int   Ln[3]    = {80, 40, 20};
    const float Lsf[3]   = {8.0f, 16.0f, 32.0f};

    int cmin[3], rmin[3], Wd[3], cum[4];
    float invW[3];
    cum[0] = 0;
#pragma unroll
    for (int L = 0; L < 3; L++) {
        const float inv_s = 1.0f / Lsf[L];
        const int c0 = max(0, (int)floorf(gx1 * inv_s) - 1);
        const int c1 = min(Ln[L] - 1, (int)ceilf(gx2 * inv_s));
        const int r0 = max(0, (int)floorf(gy1 * inv_s) - 1);
        const int r1 = min(Ln[L] - 1, (int)ceilf(gy2 * inv_s));
        const int w = c1 - c0 + 1;
        const int h = r1 - r0 + 1;
        const int cnt = (w > 0 && h > 0) ? w * h : 0;
        cmin[L] = c0; rmin[L] = r0; Wd[L] = (w > 0) ? w : 1;
        invW[L] = 1.0f / (float)Wd[L];
        cum[L + 1] = cum[L] + cnt;
    }
    const int T = cum[3];

    // per-thread register candidate store (<= NCAND candidates per thread)
    unsigned cval[NCAND], canc[NCAND];
#pragma unroll
    for (int k = 0; k < NCAND; k++) { cval[k] = 0u; canc[k] = 0xFFFFFFFFu; }
    int cnt = 0;

    for (int t = tid; t < T; t += 256) {
        const int L = (t < cum[1]) ? 0 : ((t < cum[2]) ? 1 : 2);
        const int local = t - cum[L];
        // cheap division: float reciprocal + correction (exact; local <= 1035)
        int q = (int)((float)local * invW[L]);
        int rem = local - q * Wd[L];
        if (rem < 0) { q--; rem += Wd[L]; }
        else if (rem >= Wd[L]) { q++; rem -= Wd[L]; }
        const int row = rmin[L] + q;
        const int col = cmin[L] + rem;
        const float s = Lsf[L];
        const float ax = ((float)col + 0.5f) * s;   // bit-exact vs anc input
        const float ay = ((float)row + 0.5f) * s;
        const float d = fminf(fminf(ax - gx1, ay - gy1), fminf(gx2 - ax, gy2 - ay));
        if (!(d > EPS_G)) continue;
        const int a = Lbase[L] + row * Ln[L] + col;
        const float4 p = pb[a];
        const float w2 = p.z - p.x;
        const float h2 = p.w - p.y + EPS_C;
        const float iw = fminf(gx2, p.z) - fmaxf(gx1, p.x);
        const float ih = fminf(gy2, p.w) - fmaxf(gy1, p.y);
        const float inter = fmaxf(iw, 0.0f) * fmaxf(ih, 0.0f);
        const float uni = area1 + w2 * h2 - inter + EPS_C;
        const float iou = inter / uni;
        const float cw = fmaxf(gx2, p.z) - fminf(gx1, p.x);
        const float ch = fmaxf(gy2, p.w) - fminf(gy1, p.y);
        const float c2 = cw * cw + ch * ch + EPS_C;
        const float dx = p.x + p.z - gx1 - gx2;
        const float dy = p.y + p.w - gy1 - gy2;
        const float rho2 = (dx * dx + dy * dy) * 0.25f;
        const float dat = atanf(w2 / h2) - at1;
        const float v = inv_pi2_4 * dat * dat;
        const float alpha = v / (v - iou + (1.0f + EPS_C));
        const float ciou = iou - (rho2 / c2 + v * alpha);
        const float ovl = fmaxf(ciou, 0.0f);
        if (ovl <= 0.0f) continue;
        const float sc = ps[(size_t)a * NCC + label];
        const float o2 = ovl * ovl;
        const float met = sqrtf(sc) * (o2 * o2 * o2);
        if (met > EPS_G) {
#pragma unroll
            for (int k = 0; k < NCAND; k++)
                if (cnt == k) { cval[k] = __float_as_uint(met); canc[k] = (unsigned)a; }
            cnt++;
        }
    }

    // ---- sort the <=5 register candidates descending by (v, then a asc) ----
#define CSWAP(i, j) { \
        const bool sw = (cval[j] > cval[i]) || (cval[j] == cval[i] && canc[j] < canc[i]); \
        const unsigned tv = sw ? cval[j] : cval[i]; \
        const unsigned ta = sw ? canc[j] : canc[i]; \
        cval[j] = sw ? cval[i] : cval[j]; \
        canc[j] = sw ? canc[i] : canc[j]; \
        cval[i] = tv; canc[i] = ta; }
    CSWAP(0, 1) CSWAP(3, 4) CSWAP(2, 4) CSWAP(2, 3) CSWAP(1, 4)
    CSWAP(0, 3) CSWAP(0, 2) CSWAP(1, 3) CSWAP(1, 2)
#undef CSWAP

    // ---- per-warp sorted top-10 via 10 REDUX rounds (no block barriers) ----
#pragma unroll
    for (int r = 0; r < TOPK_K; r++) {
        const unsigned bv = cval[0];
        const unsigned ba = canc[0];
        const unsigned vmax = __reduce_max_sync(full, bv);
        const unsigned acand = (bv == vmax) ? ba : 0xFFFFFFFFu;
        const unsigned amin = __reduce_min_sync(full, acand);
        if (lane == 0) { s_wtv[warp][r] = vmax; s_wta[warp][r] = amin; }
        // winner thread shifts its sorted list down one
        if (bv == vmax && ba == amin) {
#pragma unroll
            for (int k = 0; k < NCAND - 1; k++) { cval[k] = cval[k + 1]; canc[k] = canc[k + 1]; }
            cval[NCAND - 1] = 0u; canc[NCAND - 1] = 0xFFFFFFFFu;
        }
    }
    __syncthreads();

    // ---- warp 0: merge 8 sorted lists of 10 via xor-shuffle over 8 heads ----
    if (warp == 0) {
        int ptr = 0;
        int winners[TOPK_K];
        int kept = 0;
#pragma unroll
        for (int r = 0; r < TOPK_K; r++) {
            unsigned v = 0u, a = 0xFFFFFFFFu;
            if (lane < 8 && ptr < TOPK_K) { v = s_wtv[lane][ptr]; a = s_wta[lane][ptr]; }
            unsigned wv = v, wa = a;
#pragma unroll
            for (int off = 4; off; off >>= 1) {
                const unsigned ov = __shfl_xor_sync(full, wv, off);
                const unsigned oa = __shfl_xor_sync(full, wa, off);
                if (ov > wv || (ov == wv && oa < wa)) { wv = ov; wa = oa; }
            }
            if (v == wv && a == wa && lane < 8 && wv != 0u) ptr++;
            if (lane == 0) {
                winners[r] = (int)wa;
                if (__uint_as_float(wv) > EPS_G) kept = r + 1;
            }
        }
        if (lane == 0) {
            // reference quirk: dropped top-k slots scatter into anchor 0,
            // gated by mask_in_gts[0] & mask_pos_gt[0]
            if (kept < TOPK_K) {
                const float d0 = fminf(fminf(4.0f - gx1, 4.0f - gy1),
                                       fminf(gx2 - 4.0f, gy2 - 4.0f));
                if (d0 > EPS_G) winners[kept++] = 0;
            }
#pragma unroll
            for (int k = 0; k < WSTRIDE; k++)
                g_win[bm * WSTRIDE + k] = (k < kept) ? winners[k] : -1;
        }
    }
}

// ---- Phase 2 (fused): zero scores + resolve + bbox/fg + last-block scatter --
__global__ void __launch_bounds__(256)
phase2_kernel(const float* __restrict__ pd_scores,
              const float* __restrict__ pd_bboxes,
              const float* __restrict__ anc,
              const int* __restrict__ gt_labels,
              const float* __restrict__ gt_bboxes,
              const float* __restrict__ mask_gt,
              float* __restrict__ out_bboxes,
              float* __restrict__ out_scores,
              float* __restrict__ out_fg)
{
    __shared__ float4 s_gt[MM];
    __shared__ int s_lb[MM];
    __shared__ int s_ok[MM];
    __shared__ unsigned long long s_bits[256];
    __shared__ int s_last;

    const int b = blockIdx.x / NCHUNK;
    const int chunk = blockIdx.x - b * NCHUNK;
    const int tid = threadIdx.x;
    const int a0 = chunk * 256;
    const int R = min(256, AA - a0);

    // dense zero-fill of this block's score strip (R anchors x 80 = R*20 float4)
    // Independent of everything; stores fly while the resolve loads are in flight.
    {
        float4* dst = (float4*)(out_scores + ((size_t)b * AA + a0) * NCC);
        const float4 z4 = make_float4(0.0f, 0.0f, 0.0f, 0.0f);
        const int tot = R * 20;
        for (int j = tid; j < tot; j += 256) dst[j] = z4;
    }

    if (tid < MM) {
        s_gt[tid] = ((const float4*)gt_bboxes)[b * MM + tid];
        s_lb[tid] = gt_labels[b * MM + tid];
        s_ok[tid] = mask_gt[b * MM + tid] > 0.0f;
    }
    s_bits[tid] = 0ull;
    __syncthreads();

    // membership from winner lists
    for (int j = tid; j < MM * WSTRIDE; j += 256) {
        const int w = g_win[b * MM * WSTRIDE + j];
        if (w >= a0 && w < a0 + 256)
            atomicOr(&s_bits[w - a0], 1ull << (j / WSTRIDE));
    }
    __syncthreads();

    const int a = a0 + tid;
    const int i = b * AA + a;

    if (a < AA) {
        const unsigned long long bits = s_bits[tid];
        int tgt = 0, fg = 0;
        float num = 0.0f;

        if (bits) {
            fg = 1;
            const float2 an = ((const float2*)anc)[a];
            const float4 p = ((const float4*)pd_bboxes)[(size_t)b * AA + a];
            if (__popcll(bits) == 1) {
                tgt = __ffsll((long long)bits) - 1;
            } else {
                // argmax over ALL m of masked clipped CIoU (first max wins)
                float best = -1.0f;
                int bi = 0;
                for (int mm = 0; mm < MM; mm++) {
                    float v = 0.0f;
                    if (s_ok[mm]) {
                        const float4 g = s_gt[mm];
                        const float d = fminf(fminf(an.x - g.x, an.y - g.y),
                                              fminf(g.z - an.x, g.w - an.y));
                        if (d > EPS_G) {
                            const float c = ciou_full(g.x, g.y, g.z, g.w,
                                                      p.x, p.y, p.z, p.w);
                            v = fmaxf(c, 0.0f);
                        }
                    }
                    if (v > best) { best = v; bi = mm; }
                }
                tgt = bi;
            }
            float ovl = 0.0f;
            const float4 g = s_gt[tgt];
            bool pos = false;
            if (s_ok[tgt]) {
                const float d = fminf(fminf(an.x - g.x, an.y - g.y),
                                      fminf(g.z - an.x, g.w - an.y));
                pos = d > EPS_G;
            }
            if (pos) {
                const float c = ciou_full(g.x, g.y, g.z, g.w, p.x, p.y, p.z, p.w);
                ovl = fmaxf(c, 0.0f);
                const float sc = pd_scores[((size_t)b * AA + a) * NCC + s_lb[tgt]];
                const float o2 = ovl * ovl;
                num = sqrtf(sc) * (o2 * o2 * o2);
            }
            atomicMax(&g_posal[b * MM + tgt], __float_as_int(num));
            atomicMax(&g_posov[b * MM + tgt], __float_as_int(ovl));
            // append to fg list for the batch-final score scatter
            int lab = s_lb[tgt];
            if (lab < 0) lab = 0;
            const int slot = atomicAdd(&g_cnt[b], 1);
            if (slot < CAPL) {
                g_la[b * CAPL + slot] = a | (tgt << 14) | (lab << 20);
                g_ln[b * CAPL + slot] = num;
            }
        }
        ((float4*)out_bboxes)[i] = s_gt[tgt];
        out_fg[i] = fg ? 1.0f : 0.0f;
    }

    // ---- per-batch completion: last block of batch b scatters its scores ----
    __threadfence();
    __syncthreads();
    if (tid == 0) {
        const int old = atomicAdd(&g_done[b], 1);
        s_last = (old == NCHUNK - 1) ? 1 : 0;
    }
    __syncthreads();
    if (s_last) {
        __threadfence();   // acquire: zeros, pos arrays, fg lists of batch b
        const int n = min(g_cnt[b], CAPL);
        for (int k = tid; k < n; k += 256) {
            const int e = g_la[b * CAPL + k];
            const int aa = e & 0x3FFF;
            const int tgt = (e >> 14) & 63;
            const int lab = (e >> 20) & 127;
            const float pa = __int_as_float(g_posal[b * MM + tgt]);
            const float po = __int_as_float(g_posov[b * MM + tgt]);
            const float norm = g_ln[b * CAPL + k] * po / (pa + EPS_G);
            out_scores[((size_t)b * AA + aa) * NCC + lab] = norm;
        }
    }
}

extern "C" void kernel_launch(void* const* d_in, const int* in_sizes, int n_in,
                              void* d_out, int out_size)
{
    const float* pd_scores = (const float*)d_in[0];   // (B, A, NC) f32
    const float* pd_bboxes = (const float*)d_in[1];   // (B, A, 4)  f32
    const float* anc       = (const float*)d_in[2];   // (A, 2)     f32
    const int*   gt_labels = (const int*)  d_in[3];   // (B, M, 1)  i32
    const float* gt_bboxes = (const float*)d_in[4];   // (B, M, 4)  f32
    const float* mask_gt   = (const float*)d_in[5];   // (B, M, 1)  f32

    float* out = (float*)d_out;
    float* out_bboxes = out;                                  // B*A*4
    float* out_scores = out + (size_t)BB * AA * 4;            // B*A*NC
    float* out_fg     = out + (size_t)BB * AA * (4 + NCC);    // B*A

    phase1_kernel<<<BB * MM, 256>>>(pd_scores, pd_bboxes,
                                    gt_labels, gt_bboxes, mask_gt);
    phase2_kernel<<<BB * NCHUNK, 256>>>(pd_scores, pd_bboxes, anc,
                                        gt_labels, gt_bboxes, mask_gt,
                                        out_bboxes, out_scores, out_fg);
}

// round 15
// speedup vs baseline: 1.2182x; 1.1404x over previous
#include <cuda_runtime.h>
#include <math.h>

#define BB 16
#define AA 8400
#define MM 64
#define NCC 80
#define TOPK_K 10
#define EPS_G 1e-9f
#define EPS_C 1e-7f
#define NCH3 66                // phase3: ceil(8400/128)
#define WSTRIDE 12             // winners per gt: 10 topk + 1 quirk + pad
#define CAPL 768               // max fg entries per batch (<= winner slots)
#define NCAND 5                // max candidates per thread (ceil(1035/256))

// -------- scratch (device globals; no allocation allowed) --------
__device__ int g_win[BB * MM * WSTRIDE];        // winner anchors, -1 = empty
__device__ unsigned long long g_bits[BB * AA];  // claim bits (zeroed by phase3)
__device__ int g_posal[BB * MM];                // pos_align   (float bits, >=0)
__device__ int g_posov[BB * MM];                // pos_overlap (float bits, >=0)
__device__ int g_cnt[BB];                       // fg list counts
__device__ int g_la[BB * CAPL];                 // fg: a | tgt<<14 | lab<<20
__device__ float g_ln[BB * CAPL];               // fg: align metric (num)

__device__ __forceinline__ float ciou_full(float gx1, float gy1, float gx2, float gy2,
                                           float px1, float py1, float px2, float py2)
{
    const float w1 = gx2 - gx1;
    const float h1 = gy2 - gy1 + EPS_C;
    const float w2 = px2 - px1;
    const float h2 = py2 - py1 + EPS_C;
    const float iw = fminf(gx2, px2) - fmaxf(gx1, px1);
    const float ih = fminf(gy2, py2) - fmaxf(gy1, py1);
    const float inter = fmaxf(iw, 0.0f) * fmaxf(ih, 0.0f);
    const float uni = w1 * h1 + w2 * h2 - inter + EPS_C;
    const float iou = inter / uni;
    const float cw = fmaxf(gx2, px2) - fminf(gx1, px1);
    const float ch = fmaxf(gy2, py2) - fminf(gy1, py1);
    const float c2 = cw * cw + ch * ch + EPS_C;
    const float dx = px1 + px2 - gx1 - gx2;
    const float dy = py1 + py2 - gy1 - gy2;
    const float rho2 = (dx * dx + dy * dy) * 0.25f;
    const float dat = atanf(w2 / h2) - atanf(w1 / h1);
    const float v = (4.0f / (float)(M_PI * M_PI)) * dat * dat;
    const float alpha = v / (v - iou + (1.0f + EPS_C));
    return iou - (rho2 / c2 + v * alpha);
}

// ---------------- Phase 1: per-(b,m) enumerate in-box anchors, topk ----------
__global__ void __launch_bounds__(256)
phase1_kernel(const float* __restrict__ pd_scores,
              const float* __restrict__ pd_bboxes,
              const int* __restrict__ gt_labels,
              const float* __restrict__ gt_bboxes,
              const float* __restrict__ mask_gt)
{
    __shared__ unsigned s_wtv[8][TOPK_K];
    __shared__ unsigned s_wta[8][TOPK_K];

    const int bm = blockIdx.x;
    const int b = bm >> 6;
    const int m = bm & 63;
    const int tid = threadIdx.x;
    const int warp = tid >> 5;
    const int lane = tid & 31;
    const unsigned full = 0xffffffffu;

    if (tid == 0) {
        g_posal[bm] = 0;
        g_posov[bm] = 0;
        if (m == 0) g_cnt[b] = 0;
    }

    const bool valid = mask_gt[bm] > 0.0f;
    if (!valid) {
        // metrics all zero -> no winners, no quirk (mask_pos_gt[0] is 0)
        if (tid < WSTRIDE) g_win[bm * WSTRIDE + tid] = -1;
        return;
    }

    const float4 gb = ((const float4*)gt_bboxes)[bm];
    const float gx1 = gb.x, gy1 = gb.y, gx2 = gb.z, gy2 = gb.w;
    const int   label = gt_labels[bm];

    const float w1 = gx2 - gx1;
    const float h1 = gy2 - gy1 + EPS_C;
    const float area1 = w1 * h1;
    const float at1 = atanf(w1 / h1);
    const float inv_pi2_4 = 4.0f / (float)(M_PI * M_PI);

    const float4* pb = (const float4*)(pd_bboxes + (size_t)b * AA * 4);
    const float*  ps = pd_scores + (size_t)b * AA * NCC;

    // anchor lattice: level L has n=640/s points per axis at ((c+0.5)*s)
    const int   Lbase[3] = {0, 6400, 8000};
    const int   Ln[3]    = {80, 40, 20};
    const float Lsf[3]   = {8.0f, 16.0f, 32.0f};

    int cmin[3], rmin[3], Wd[3], cum[4];
    float invW[3];
    cum[0] = 0;
#pragma unroll
    for (int L = 0; L < 3; L++) {
        const float inv_s = 1.0f / Lsf[L];
        const int c0 = max(0, (int)floorf(gx1 * inv_s) - 1);
        const int c1 = min(Ln[L] - 1, (int)ceilf(gx2 * inv_s));
        const int r0 = max(0, (int)floorf(gy1 * inv_s) - 1);
        const int r1 = min(Ln[L] - 1, (int)ceilf(gy2 * inv_s));
        const int w = c1 - c0 + 1;
        const int h = r1 - r0 + 1;
        const int cnt = (w > 0 && h > 0) ? w * h : 0;
        cmin[L] = c0; rmin[L] = r0; Wd[L] = (w > 0) ? w : 1;
        invW[L] = 1.0f / (float)Wd[L];
        cum[L + 1] = cum[L] + cnt;
    }
    const int T = cum[3];

    // per-thread register candidate store (<= NCAND candidates per thread)
    unsigned cval[NCAND], canc[NCAND];
#pragma unroll
    for (int k = 0; k < NCAND; k++) { cval[k] = 0u; canc[k] = 0xFFFFFFFFu; }
    int cnt = 0;

    for (int t = tid; t < T; t += 256) {
        const int L = (t < cum[1]) ? 0 : ((t < cum[2]) ? 1 : 2);
        const int local = t - cum[L];
        // cheap division: float reciprocal + correction (exact; local <= 1035)
        int q = (int)((float)local * invW[L]);
        int rem = local - q * Wd[L];
        if (rem < 0) { q--; rem += Wd[L]; }
        else if (rem >= Wd[L]) { q++; rem -= Wd[L]; }
        const int row = rmin[L] + q;
        const int col = cmin[L] + rem;
        const float s = Lsf[L];
        const float ax = ((float)col + 0.5f) * s;   // bit-exact vs anc input
        const float ay = ((float)row + 0.5f) * s;
        const float d = fminf(fminf(ax - gx1, ay - gy1), fminf(gx2 - ax, gy2 - ay));
        if (!(d > EPS_G)) continue;
        const int a = Lbase[L] + row * Ln[L] + col;
        const float4 p = pb[a];
        const float w2 = p.z - p.x;
        const float h2 = p.w - p.y + EPS_C;
        const float iw = fminf(gx2, p.z) - fmaxf(gx1, p.x);
        const float ih = fminf(gy2, p.w) - fmaxf(gy1, p.y);
        const float inter = fmaxf(iw, 0.0f) * fmaxf(ih, 0.0f);
        const float uni = area1 + w2 * h2 - inter + EPS_C;
        const float iou = inter / uni;
        const float cw = fmaxf(gx2, p.z) - fminf(gx1, p.x);
        const float ch = fmaxf(gy2, p.w) - fminf(gy1, p.y);
        const float c2 = cw * cw + ch * ch + EPS_C;
        const float dx = p.x + p.z - gx1 - gx2;
        const float dy = p.y + p.w - gy1 - gy2;
        const float rho2 = (dx * dx + dy * dy) * 0.25f;
        const float dat = atanf(w2 / h2) - at1;
        const float v = inv_pi2_4 * dat * dat;
        const float alpha = v / (v - iou + (1.0f + EPS_C));
        const float ciou = iou - (rho2 / c2 + v * alpha);
        const float ovl = fmaxf(ciou, 0.0f);
        if (ovl <= 0.0f) continue;
        const float sc = ps[(size_t)a * NCC + label];
        const float o2 = ovl * ovl;
        const float met = sqrtf(sc) * (o2 * o2 * o2);
        if (met > EPS_G) {
#pragma unroll
            for (int k = 0; k < NCAND; k++)
                if (cnt == k) { cval[k] = __float_as_uint(met); canc[k] = (unsigned)a; }
            cnt++;
        }
    }

    // ---- sort the <=5 register candidates descending by (v, then a asc) ----
#define CSWAP(i, j) { \
        const bool sw = (cval[j] > cval[i]) || (cval[j] == cval[i] && canc[j] < canc[i]); \
        const unsigned tv = sw ? cval[j] : cval[i]; \
        const unsigned ta = sw ? canc[j] : canc[i]; \
        cval[j] = sw ? cval[i] : cval[j]; \
        canc[j] = sw ? canc[i] : canc[j]; \
        cval[i] = tv; canc[i] = ta; }
    CSWAP(0, 1) CSWAP(3, 4) CSWAP(2, 4) CSWAP(2, 3) CSWAP(1, 4)
    CSWAP(0, 3) CSWAP(0, 2) CSWAP(1, 3) CSWAP(1, 2)
#undef CSWAP

    // ---- per-warp sorted top-10 via 10 REDUX rounds (no block barriers) ----
#pragma unroll
    for (int r = 0; r < TOPK_K; r++) {
        const unsigned bv = cval[0];
        const unsigned ba = canc[0];
        const unsigned vmax = __reduce_max_sync(full, bv);
        const unsigned acand = (bv == vmax) ? ba : 0xFFFFFFFFu;
        const unsigned amin = __reduce_min_sync(full, acand);
        if (lane == 0) { s_wtv[warp][r] = vmax; s_wta[warp][r] = amin; }
        // winner thread shifts its sorted list down one
        if (bv == vmax && ba == amin) {
#pragma unroll
            for (int k = 0; k < NCAND - 1; k++) { cval[k] = cval[k + 1]; canc[k] = canc[k + 1]; }
            cval[NCAND - 1] = 0u; canc[NCAND - 1] = 0xFFFFFFFFu;
        }
    }
    __syncthreads();

    // ---- warp 0: merge 8 sorted lists of 10 via xor-shuffle over 8 heads ----
    if (warp == 0) {
        int ptr = 0;
        int winners[TOPK_K];
        int kept = 0;
#pragma unroll
        for (int r = 0; r < TOPK_K; r++) {
            unsigned v = 0u, a = 0xFFFFFFFFu;
            if (lane < 8 && ptr < TOPK_K) { v = s_wtv[lane][ptr]; a = s_wta[lane][ptr]; }
            unsigned wv = v, wa = a;
#pragma unroll
            for (int off = 4; off; off >>= 1) {
                const unsigned ov = __shfl_xor_sync(full, wv, off);
                const unsigned oa = __shfl_xor_sync(full, wa, off);
                if (ov > wv || (ov == wv && oa < wa)) { wv = ov; wa = oa; }
            }
            if (v == wv && a == wa && lane < 8 && wv != 0u) ptr++;
            if (lane == 0) {
                winners[r] = (int)wa;
                if (__uint_as_float(wv) > EPS_G) kept = r + 1;
            }
        }
        if (lane == 0) {
            // reference quirk: dropped top-k slots scatter into anchor 0,
            // gated by mask_in_gts[0] & mask_pos_gt[0]
            if (kept < TOPK_K) {
                const float d0 = fminf(fminf(4.0f - gx1, 4.0f - gy1),
                                       fminf(gx2 - 4.0f, gy2 - 4.0f));
                if (d0 > EPS_G) winners[kept++] = 0;
            }
#pragma unroll
            for (int k = 0; k < WSTRIDE; k++) {
                const int w = (k < kept) ? winners[k] : -1;
                g_win[bm * WSTRIDE + k] = w;
                if (w >= 0)
                    atomicOr(&g_bits[(size_t)b * AA + w], 1ull << m);
            }
        }
    }
}

// ---------------- K2: warp-per-entry sparse resolve --------------------------
__global__ void __launch_bounds__(384)
resolve_kernel(const float* __restrict__ pd_scores,
               const float* __restrict__ pd_bboxes,
               const float* __restrict__ anc,
               const int* __restrict__ gt_labels,
               const float* __restrict__ gt_bboxes,
               const float* __restrict__ mask_gt)
{
    __shared__ float4 s_gt[MM];
    __shared__ int s_lb[MM];
    __shared__ int s_ok[MM];

    const int bm = blockIdx.x;
    const int b = bm >> 6;
    const int m = bm & 63;
    const int tid = threadIdx.x;
    const int warp = tid >> 5;        // 12 warps = 12 winner slots
    const int lane = tid & 31;
    const unsigned full = 0xffffffffu;

    if (tid < MM) {
        s_gt[tid] = ((const float4*)gt_bboxes)[b * MM + tid];
        s_lb[tid] = gt_labels[b * MM + tid];
        s_ok[tid] = mask_gt[b * MM + tid] > 0.0f;
    }
    __syncthreads();

    const int a = g_win[bm * WSTRIDE + warp];
    if (a < 0) return;
    const unsigned long long bits = g_bits[(size_t)b * AA + a];
    if (m != __ffsll((long long)bits) - 1) return;   // owner = lowest claimant

    const float2 an = ((const float2*)anc)[a];
    const float4 p = ((const float4*)pd_bboxes)[(size_t)b * AA + a];

    int tgt;
    if (__popcll(bits) == 1) {
        tgt = m;
    } else {
        // warp-parallel argmax over ALL m of masked clipped CIoU
        // (max value, then lowest m -> identical to serial first-max-wins)
        unsigned myv = 0u;
        int mym = lane;
#pragma unroll
        for (int h = 0; h < 2; h++) {
            const int mm = lane + h * 32;
            float v = 0.0f;
            if (s_ok[mm]) {
                const float4 g = s_gt[mm];
                const float d = fminf(fminf(an.x - g.x, an.y - g.y),
                                      fminf(g.z - an.x, g.w - an.y));
                if (d > EPS_G) {
                    const float c = ciou_full(g.x, g.y, g.z, g.w, p.x, p.y, p.z, p.w);
                    v = fmaxf(c, 0.0f);
                }
            }
            const unsigned vb = __float_as_uint(v);   // v >= 0 -> monotonic bits
            if (h == 0) { myv = vb; }
            else if (vb > myv) { myv = vb; mym = mm; }
        }
        const unsigned vmax = __reduce_max_sync(full, myv);
        const unsigned mcand = (myv == vmax) ? (unsigned)mym : 0xFFFFFFFFu;
        tgt = (int)__reduce_min_sync(full, mcand);
    }

    if (lane == 0) {
        float ovl = 0.0f, num = 0.0f;
        const float4 g = s_gt[tgt];
        bool pos = false;
        if (s_ok[tgt]) {
            const float d = fminf(fminf(an.x - g.x, an.y - g.y),
                                  fminf(g.z - an.x, g.w - an.y));
            pos = d > EPS_G;
        }
        if (pos) {
            const float c = ciou_full(g.x, g.y, g.z, g.w, p.x, p.y, p.z, p.w);
            ovl = fmaxf(c, 0.0f);
            const float sc = pd_scores[((size_t)b * AA + a) * NCC + s_lb[tgt]];
            const float o2 = ovl * ovl;
            num = sqrtf(sc) * (o2 * o2 * o2);
        }
        atomicMax(&g_posal[b * MM + tgt], __float_as_int(num));
        atomicMax(&g_posov[b * MM + tgt], __float_as_int(ovl));
        int lab = s_lb[tgt];
        if (lab < 0) lab = 0;
        const int slot = atomicAdd(&g_cnt[b], 1);
        if (slot < CAPL) {
            g_la[b * CAPL + slot] = a | (tgt << 14) | (lab << 20);
            g_ln[b * CAPL + slot] = num;
        }
    }
}

// ------- K3: dense defaults + sparse overrides (one pass over outputs) -------
__global__ void __launch_bounds__(256)
phase3_kernel(const float* __restrict__ gt_bboxes,
              float* __restrict__ out_bboxes,
              float* __restrict__ out_scores,
              float* __restrict__ out_fg)
{
    __shared__ float4 s_gt[MM];
    __shared__ int s_ent[CAPL];
    __shared__ float s_num[CAPL];

    const int b = blockIdx.x / NCH3;
    const int chunk = blockIdx.x - b * NCH3;
    const int tid = threadIdx.x;
    const int a0 = chunk * 128;
    const int R = min(128, AA - a0);

    if (tid < MM) s_gt[tid] = ((const float4*)gt_bboxes)[b * MM + tid];
    const int n = min(g_cnt[b], CAPL);
    for (int j = tid; j < n; j += 256) {
        s_ent[j] = g_la[b * CAPL + j];
        s_num[j] = g_ln[b * CAPL + j];
    }

    // dense defaults: zero scores strip, bbox = gt[b][0], fg = 0
    {
        float4* dst = (float4*)(out_scores + ((size_t)b * AA + a0) * NCC);
        const float4 z4 = make_float4(0.0f, 0.0f, 0.0f, 0.0f);
        const int tot = R * 20;
        for (int j = tid; j < tot; j += 256) dst[j] = z4;
    }
    __syncthreads();   // s_gt ready; also orders default stores before overrides
    if (tid < R) {
        const size_t i = (size_t)b * AA + a0 + tid;
        ((float4*)out_bboxes)[i] = s_gt[0];
        out_fg[i] = 0.0f;
        g_bits[i] = 0ull;          // reset claims for the next replay
    }
    __syncthreads();

    // sparse overrides for claimed anchors in this strip
    for (int j = tid; j < n; j += 256) {
        const int e = s_ent[j];
        const int a = e & 0x3FFF;
        if (a < a0 || a >= a0 + R) continue;
        const int tgt = (e >> 14) & 63;
        const int lab = (e >> 20) & 127;
        const float pa = __int_as_float(g_posal[b * MM + tgt]);
        const float po = __int_as_float(g_posov[b * MM + tgt]);
        const float norm = s_num[j] * po / (pa + EPS_G);
        const size_t i = (size_t)b * AA + a;
        ((float4*)out_bboxes)[i] = s_gt[tgt];
        out_fg[i] = 1.0f;
        out_scores[i * NCC + lab] = norm;
    }
}

extern "C" void kernel_launch(void* const* d_in, const int* in_sizes, int n_in,
                              void* d_out, int out_size)
{
    const float* pd_scores = (const float*)d_in[0];   // (B, A, NC) f32
    const float* pd_bboxes = (const float*)d_in[1];   // (B, A, 4)  f32
    const float* anc       = (const float*)d_in[2];   // (A, 2)     f32
    const int*   gt_labels = (const int*)  d_in[3];   // (B, M, 1)  i32
    const float* gt_bboxes = (const float*)d_in[4];   // (B, M, 4)  f32
    const float* mask_gt   = (const float*)d_in[5];   // (B, M, 1)  f32

    float* out = (float*)d_out;
    float* out_bboxes = out;                                  // B*A*4
    float* out_scores = out + (size_t)BB * AA * 4;            // B*A*NC
    float* out_fg     = out + (size_t)BB * AA * (4 + NCC);    // B*A

    phase1_kernel<<<BB * MM, 256>>>(pd_scores, pd_bboxes,
                                    gt_labels, gt_bboxes, mask_gt);
    resolve_kernel<<<BB * MM, 384>>>(pd_scores, pd_bboxes, anc,
                                     gt_labels, gt_bboxes, mask_gt);
    phase3_kernel<<<BB * NCH3, 256>>>(gt_bboxes, out_bboxes,
                                      out_scores, out_fg);
}